// round 3
// baseline (speedup 1.0000x reference)
#include <cuda_runtime.h>
#include <cuda_bf16.h>
#include <cstdint>

#define N_NODES 100000
#define N_EDGES 1600000

// ---------------- scratch (device globals; no allocations) ----------------
__device__ float g_sum[(size_t)N_NODES * 64];   // aggregation accumulator (both layers)
__device__ float g_deg[N_NODES];                // in-degree (float)
__device__ float g_inv[N_NODES];                // 1/max(deg,1), precomputed
__device__ float g_h[(size_t)N_NODES * 64];     // layer-1 output (relu)
__device__ int   g_is64;                        // edge_index element width flag

// ---------------- dtype width detection for edge_index ----------------
__global__ void detect_kernel(const int* __restrict__ ei32) {
    int odd_nonzero = 0;
    #pragma unroll 8
    for (int i = 0; i < 256; i += 2) {
        if (ei32[i + 1] != 0) odd_nonzero = 1;
    }
    g_is64 = odd_nonzero ? 0 : 1;
}

// ---------------- zero kernels ----------------
__global__ void zero_sum_deg_kernel() {
    int i = blockIdx.x * blockDim.x + threadIdx.x;
    const int n_sum4 = (N_NODES * 64) / 4;
    const int n_deg4 = N_NODES / 4;
    if (i < n_sum4) {
        ((float4*)g_sum)[i] = make_float4(0.f, 0.f, 0.f, 0.f);
    } else if (i < n_sum4 + n_deg4) {
        ((float4*)g_deg)[i - n_sum4] = make_float4(0.f, 0.f, 0.f, 0.f);
    }
}

__global__ void zero_sum_kernel() {
    int i = blockIdx.x * blockDim.x + threadIdx.x;
    if (i < (N_NODES * 64) / 4) {
        ((float4*)g_sum)[i] = make_float4(0.f, 0.f, 0.f, 0.f);
    }
}

// ---------------- inv-degree precompute ----------------
__global__ void inv_kernel() {
    int i = blockIdx.x * blockDim.x + threadIdx.x;
    if (i < N_NODES) g_inv[i] = 1.0f / fmaxf(g_deg[i], 1.0f);
}

// ---------------- edge scatter (segment-sum via vector reduction) ----------------
__global__ void scatter_kernel(const float* __restrict__ feat_ext,
                               const void*  __restrict__ ei,
                               int use_h, int do_deg) {
    long long tid = (long long)blockIdx.x * blockDim.x + threadIdx.x;
    if (tid >= (long long)N_EDGES * 16) return;
    int e = (int)(tid >> 4);
    int c = (int)(tid & 15);

    int src, dst;
    if (g_is64) {
        const long long* p = (const long long*)ei;
        src = (int)p[e];
        dst = (int)p[N_EDGES + e];
    } else {
        const int* p = (const int*)ei;
        src = p[e];
        dst = p[N_EDGES + e];
    }

    const float* feat = use_h ? g_h : feat_ext;
    float4 v = ((const float4*)(feat + (size_t)src * 64))[c];
    float* pdst = g_sum + (size_t)dst * 64 + c * 4;
    asm volatile("red.global.add.v4.f32 [%0], {%1,%2,%3,%4};"
                 :: "l"(pdst), "f"(v.x), "f"(v.y), "f"(v.z), "f"(v.w)
                 : "memory");

    if (do_deg && c == 0) {
        atomicAdd(&g_deg[dst], 1.0f);
    }
}

// ---------------- packed-f32x2 fused dual GEMM, register-blocked 2x16 ----------------
// out[n][:] = relu?( mean(n) @ Wn + feat(n) @ Ws + b ),  K = 128 (virtual concat).
// 256 threads, 128 nodes/block. Thread (ln = tid>>2, q = tid&3) computes nodes
// {base+ln, base+ln+64} x outputs {j8*16 + q*4 + 0..3}.
// K tiled in 4 chunks of 32; per chunk features staged to smem (pitch 36 ->
// conflict-free broadcast reads), weights staged [32][OUT].
// Inner loop per k: 2 LDS.32 (features) + JB LDS.128 (weights) + 4*JB FFMA2.
#define FMA2(acc, a2, b2) \
    asm("fma.rn.f32x2 %0, %1, %2, %0;" : "+l"(acc) : "l"(a2), "l"(b2))

template<int OUT>
__global__ __launch_bounds__(256)
void sage_gemm3_kernel(const float* __restrict__ feat_ext,
                       const float* __restrict__ Wn,   // [64, OUT]
                       const float* __restrict__ Ws,   // [64, OUT]
                       const float* __restrict__ bias, // [OUT]
                       float* __restrict__ out_ext,    // [N, OUT]
                       int feat_is_h, int out_is_h, int relu) {
    constexpr int JB = OUT / 16;           // 4 (OUT=64) or 2 (OUT=32)
    constexpr int PITCH = 36;              // feature row pitch (bank spread, 16B-aligned)
    __shared__ float sF[128 * PITCH];      // 18KB: 128 node rows x 32 k
    __shared__ float sW[32 * OUT];         // chunk weights [kk][OUT]

    const float* feat = feat_is_h ? g_h : feat_ext;
    float* out = out_is_h ? g_h : out_ext;
    int tid = threadIdx.x;
    int base = blockIdx.x * 128;
    int ln = tid >> 2;                     // 0..63
    int q  = tid & 3;
    int n0 = base + ln;
    int n1 = base + ln + 64;

    unsigned long long acc0[JB * 2], acc1[JB * 2];
    #pragma unroll
    for (int i = 0; i < JB * 2; i++) { acc0[i] = 0ULL; acc1[i] = 0ULL; }

    const float* fp0 = sF + ln * PITCH;
    const float* fp1 = sF + (ln + 64) * PITCH;
    const float* wq  = sW + (q << 2);

    #pragma unroll
    for (int c = 0; c < 4; c++) {
        __syncthreads();   // previous chunk's consumers done

        // stage chunk weights: rows c*32..c*32+31 of (c<2 ? Wn : Ws)
        {
            const float4* wsrc = (const float4*)((c < 2 ? Wn : Ws) + (c & 1) * 32 * OUT);
            #pragma unroll
            for (int i = tid; i < 8 * OUT; i += 256)
                ((float4*)sW)[i] = wsrc[i];
        }
        // stage chunk features: 128 rows x 32 floats (mean pre-divided for c<2)
        #pragma unroll
        for (int i = tid; i < 1024; i += 256) {
            int r  = i >> 3;
            int k4 = i & 7;
            int n  = base + r;
            int nc = (n < N_NODES) ? n : (N_NODES - 1);
            float4 v;
            if (c < 2) {
                v = *(const float4*)(g_sum + (size_t)nc * 64 + c * 32 + k4 * 4);
                float iv = g_inv[nc];
                v.x *= iv; v.y *= iv; v.z *= iv; v.w *= iv;
            } else {
                v = *(const float4*)(feat + (size_t)nc * 64 + (c - 2) * 32 + k4 * 4);
            }
            *(float4*)(sF + r * PITCH + k4 * 4) = v;
        }
        __syncthreads();

        #pragma unroll 8
        for (int kk = 0; kk < 32; kk++) {
            float f0 = fp0[kk];
            float f1 = fp1[kk];
            unsigned long long f0d, f1d;
            asm("mov.b64 %0, {%1,%1};" : "=l"(f0d) : "f"(f0));
            asm("mov.b64 %0, {%1,%1};" : "=l"(f1d) : "f"(f1));
            const float* wr = wq + kk * OUT;
            #pragma unroll
            for (int j8 = 0; j8 < JB; j8++) {
                ulonglong2 w = *(const ulonglong2*)(wr + j8 * 16);
                FMA2(acc0[j8 * 2],     f0d, w.x);
                FMA2(acc0[j8 * 2 + 1], f0d, w.y);
                FMA2(acc1[j8 * 2],     f1d, w.x);
                FMA2(acc1[j8 * 2 + 1], f1d, w.y);
            }
        }
    }

    // epilogue: unpack, +bias, relu, float4 stores
    #pragma unroll
    for (int j8 = 0; j8 < JB; j8++) {
        int jb = j8 * 16 + (q << 2);
        float bv[4];
        #pragma unroll
        for (int t = 0; t < 4; t++) bv[t] = __ldg(bias + jb + t);

        if (n0 < N_NODES) {
            float o[4];
            asm("mov.b64 {%0,%1}, %2;" : "=f"(o[0]), "=f"(o[1]) : "l"(acc0[j8 * 2]));
            asm("mov.b64 {%0,%1}, %2;" : "=f"(o[2]), "=f"(o[3]) : "l"(acc0[j8 * 2 + 1]));
            #pragma unroll
            for (int t = 0; t < 4; t++) {
                o[t] += bv[t];
                if (relu) o[t] = fmaxf(o[t], 0.0f);
            }
            *(float4*)(out + (size_t)n0 * OUT + jb) = *(float4*)o;
        }
        if (n1 < N_NODES) {
            float o[4];
            asm("mov.b64 {%0,%1}, %2;" : "=f"(o[0]), "=f"(o[1]) : "l"(acc1[j8 * 2]));
            asm("mov.b64 {%0,%1}, %2;" : "=f"(o[2]), "=f"(o[3]) : "l"(acc1[j8 * 2 + 1]));
            #pragma unroll
            for (int t = 0; t < 4; t++) {
                o[t] += bv[t];
                if (relu) o[t] = fmaxf(o[t], 0.0f);
            }
            *(float4*)(out + (size_t)n1 * OUT + jb) = *(float4*)o;
        }
    }
}

// ---------------- launch ----------------
extern "C" void kernel_launch(void* const* d_in, const int* in_sizes, int n_in,
                              void* d_out, int out_size) {
    const float* x   = (const float*)d_in[0];
    const void*  ei  = d_in[1];
    const float* W1n = (const float*)d_in[2];
    const float* W1s = (const float*)d_in[3];
    const float* b1  = (const float*)d_in[4];
    const float* W2n = (const float*)d_in[5];
    const float* W2s = (const float*)d_in[6];
    const float* b2  = (const float*)d_in[7];
    float* out = (float*)d_out;

    // 0) detect edge_index element width
    detect_kernel<<<1, 1>>>((const int*)ei);

    // 1) zero accumulator + degree
    {
        int n4 = (N_NODES * 64) / 4 + N_NODES / 4;
        zero_sum_deg_kernel<<<(n4 + 255) / 256, 256>>>();
    }

    // 2) layer-1 scatter: sum x[src] into g_sum, count degree
    {
        long long total = (long long)N_EDGES * 16;
        int blocks = (int)((total + 255) / 256);
        scatter_kernel<<<blocks, 256>>>(x, ei, /*use_h=*/0, /*do_deg=*/1);
    }

    // 2b) precompute 1/max(deg,1)
    inv_kernel<<<(N_NODES + 255) / 256, 256>>>();

    // 3) layer-1 transform: g_h = relu(mean@W1n + x@W1s + b1)
    {
        int blocks = (N_NODES + 127) / 128;
        sage_gemm3_kernel<64><<<blocks, 256>>>(x, W1n, W1s, b1, nullptr,
                                               /*feat_is_h=*/0, /*out_is_h=*/1, /*relu=*/1);
    }

    // 4) re-zero accumulator
    {
        int n4 = (N_NODES * 64) / 4;
        zero_sum_kernel<<<(n4 + 255) / 256, 256>>>();
    }

    // 5) layer-2 scatter: sum g_h[src] into g_sum
    {
        long long total = (long long)N_EDGES * 16;
        int blocks = (int)((total + 255) / 256);
        scatter_kernel<<<blocks, 256>>>(nullptr, ei, /*use_h=*/1, /*do_deg=*/0);
    }

    // 6) layer-2 transform: out = mean2@W2n + g_h@W2s + b2
    {
        int blocks = (N_NODES + 127) / 128;
        sage_gemm3_kernel<32><<<blocks, 256>>>(nullptr, W2n, W2s, b2, out,
                                               /*feat_is_h=*/1, /*out_is_h=*/0, /*relu=*/0);
    }
}

// round 4
// speedup vs baseline: 1.5014x; 1.5014x over previous
#include <cuda_runtime.h>
#include <cuda_bf16.h>
#include <cstdint>

#define N_NODES 100000
#define N_EDGES 1600000

// ---------------- scratch (device globals; no allocations) ----------------
__device__ float g_sum[(size_t)N_NODES * 64];   // aggregation accumulator (both layers)
__device__ float g_deg[N_NODES];                // in-degree (float)
__device__ float g_inv[N_NODES];                // 1/max(deg,1), precomputed
__device__ float g_h[(size_t)N_NODES * 64];     // layer-1 output (relu)
__device__ int   g_is64;                        // edge_index element width flag

// ---------------- dtype width detection for edge_index ----------------
__global__ void detect_kernel(const int* __restrict__ ei32) {
    int odd_nonzero = 0;
    #pragma unroll 8
    for (int i = 0; i < 256; i += 2) {
        if (ei32[i + 1] != 0) odd_nonzero = 1;
    }
    g_is64 = odd_nonzero ? 0 : 1;
}

// ---------------- zero kernels ----------------
__global__ void zero_sum_deg_kernel() {
    int i = blockIdx.x * blockDim.x + threadIdx.x;
    const int n_sum4 = (N_NODES * 64) / 4;
    const int n_deg4 = N_NODES / 4;
    if (i < n_sum4) {
        ((float4*)g_sum)[i] = make_float4(0.f, 0.f, 0.f, 0.f);
    } else if (i < n_sum4 + n_deg4) {
        ((float4*)g_deg)[i - n_sum4] = make_float4(0.f, 0.f, 0.f, 0.f);
    }
}

__global__ void zero_sum_kernel() {
    int i = blockIdx.x * blockDim.x + threadIdx.x;
    if (i < (N_NODES * 64) / 4) {
        ((float4*)g_sum)[i] = make_float4(0.f, 0.f, 0.f, 0.f);
    }
}

// ---------------- inv-degree precompute ----------------
__global__ void inv_kernel() {
    int i = blockIdx.x * blockDim.x + threadIdx.x;
    if (i < N_NODES) g_inv[i] = 1.0f / fmaxf(g_deg[i], 1.0f);
}

// ---------------- edge scatter (segment-sum via vector reduction) ----------------
__global__ void scatter_kernel(const float* __restrict__ feat_ext,
                               const void*  __restrict__ ei,
                               int use_h, int do_deg) {
    long long tid = (long long)blockIdx.x * blockDim.x + threadIdx.x;
    if (tid >= (long long)N_EDGES * 16) return;
    int e = (int)(tid >> 4);
    int c = (int)(tid & 15);

    int src, dst;
    if (g_is64) {
        const long long* p = (const long long*)ei;
        src = (int)p[e];
        dst = (int)p[N_EDGES + e];
    } else {
        const int* p = (const int*)ei;
        src = p[e];
        dst = p[N_EDGES + e];
    }

    const float* feat = use_h ? g_h : feat_ext;
    float4 v = ((const float4*)(feat + (size_t)src * 64))[c];
    float* pdst = g_sum + (size_t)dst * 64 + c * 4;
    asm volatile("red.global.add.v4.f32 [%0], {%1,%2,%3,%4};"
                 :: "l"(pdst), "f"(v.x), "f"(v.y), "f"(v.z), "f"(v.w)
                 : "memory");

    if (do_deg && c == 0) {
        atomicAdd(&g_deg[dst], 1.0f);
    }
}

// ---------------- pipelined packed-f32x2 fused dual GEMM ----------------
// out[n][:] = relu?( mean(n) @ Wn + feat(n) @ Ws + b ),  virtual K = 128.
// 256 threads, 128 nodes/block. Thread (ln=tid>>2, q=tid&3) -> nodes
// {base+ln, base+ln+64} x outputs {j8*16 + q*4 + 0..3}.
// K tiled in 4 chunks of 32; chunk c+1 globals prefetched into REGISTERS
// while chunk c computes from smem (software pipeline; latency hidden).
// Feat tile pitch 33 (conflict-free STS.32 and broadcast LDS.32);
// weights [kk][OUT] (64B-contiguous broadcast LDS.128).
#define FMA2(acc, a2, b2) \
    asm("fma.rn.f32x2 %0, %1, %2, %0;" : "+l"(acc) : "l"(a2), "l"(b2))

template<int OUT>
__global__ __launch_bounds__(256, 3)
void sage_gemm4_kernel(const float* __restrict__ feat_ext,
                       const float* __restrict__ Wn,   // [64, OUT]
                       const float* __restrict__ Ws,   // [64, OUT]
                       const float* __restrict__ bias, // [OUT]
                       float* __restrict__ out_ext,    // [N, OUT]
                       int feat_is_h, int out_is_h, int relu) {
    constexpr int JB  = OUT / 16;           // 4 (OUT=64) / 2 (OUT=32)
    constexpr int FP  = 33;                 // feat tile pitch (floats)
    constexpr int NW4 = (32 * OUT) / 1024;  // weight float4 per thread: 2 / 1
    __shared__ float sF[128 * FP];          // 16.9KB
    __shared__ float sW[32 * OUT];          // 8KB / 4KB
    __shared__ float sb[OUT];

    const float* feat = feat_is_h ? g_h : feat_ext;
    float* out = out_is_h ? g_h : out_ext;
    int tid  = threadIdx.x;
    int base = blockIdx.x * 128;
    int ln = tid >> 2;
    int q  = tid & 3;

    // staging coords (fixed per thread)
    int k4 = tid & 7;
    int r_[4], nc_[4];
    #pragma unroll
    for (int it = 0; it < 4; it++) {
        int i = tid + it * 256;
        r_[it] = i >> 3;
        int n = base + r_[it];
        nc_[it] = (n < N_NODES) ? n : (N_NODES - 1);
    }

    float4 pf[4];
    float4 pw[NW4];

    auto load_chunk = [&](int c) {
        #pragma unroll
        for (int it = 0; it < 4; it++) {
            if (c < 2) {
                const float* s = g_sum + (size_t)nc_[it] * 64 + c * 32 + k4 * 4;
                float4 v = *(const float4*)s;
                float iv = g_inv[nc_[it]];
                v.x *= iv; v.y *= iv; v.z *= iv; v.w *= iv;
                pf[it] = v;
            } else {
                const float* s = feat + (size_t)nc_[it] * 64 + (c - 2) * 32 + k4 * 4;
                pf[it] = *(const float4*)s;
            }
        }
        const float4* wsrc = (const float4*)((c < 2 ? Wn : Ws) + (c & 1) * 32 * OUT);
        #pragma unroll
        for (int iw = 0; iw < NW4; iw++) pw[iw] = wsrc[tid + iw * 256];
    };
    auto store_stage = [&]() {
        #pragma unroll
        for (int it = 0; it < 4; it++) {
            float* d = sF + r_[it] * FP + k4 * 4;
            d[0] = pf[it].x; d[1] = pf[it].y; d[2] = pf[it].z; d[3] = pf[it].w;
        }
        #pragma unroll
        for (int iw = 0; iw < NW4; iw++) ((float4*)sW)[tid + iw * 256] = pw[iw];
    };

    load_chunk(0);
    if (tid < OUT) sb[tid] = bias[tid];
    store_stage();
    __syncthreads();

    unsigned long long acc0[JB * 2] = {}, acc1[JB * 2] = {};
    const float* fp0 = sF + ln * FP;
    const float* fp1 = sF + (ln + 64) * FP;
    const float* wq  = sW + (q << 2);

    #pragma unroll 1
    for (int c = 0; c < 4; c++) {
        if (c < 3) load_chunk(c + 1);     // globals in flight during compute
        #pragma unroll 8
        for (int kk = 0; kk < 32; kk++) {
            float f0 = fp0[kk];
            float f1 = fp1[kk];
            unsigned long long f0d, f1d;
            asm("mov.b64 %0, {%1,%1};" : "=l"(f0d) : "f"(f0));
            asm("mov.b64 %0, {%1,%1};" : "=l"(f1d) : "f"(f1));
            const float* wr = wq + kk * OUT;
            #pragma unroll
            for (int j8 = 0; j8 < JB; j8++) {
                ulonglong2 w = *(const ulonglong2*)(wr + j8 * 16);
                FMA2(acc0[j8 * 2],     f0d, w.x);
                FMA2(acc0[j8 * 2 + 1], f0d, w.y);
                FMA2(acc1[j8 * 2],     f1d, w.x);
                FMA2(acc1[j8 * 2 + 1], f1d, w.y);
            }
        }
        __syncthreads();                  // consumers done before overwrite
        if (c < 3) {
            store_stage();
            __syncthreads();
        }
    }

    // epilogue: unpack, +bias, relu, float4 stores
    int n0 = base + ln;
    int n1 = base + ln + 64;
    #pragma unroll
    for (int j8 = 0; j8 < JB; j8++) {
        int jb = j8 * 16 + (q << 2);
        if (n0 < N_NODES) {
            float o[4];
            asm("mov.b64 {%0,%1}, %2;" : "=f"(o[0]), "=f"(o[1]) : "l"(acc0[j8 * 2]));
            asm("mov.b64 {%0,%1}, %2;" : "=f"(o[2]), "=f"(o[3]) : "l"(acc0[j8 * 2 + 1]));
            #pragma unroll
            for (int t = 0; t < 4; t++) {
                o[t] += sb[jb + t];
                if (relu) o[t] = fmaxf(o[t], 0.0f);
            }
            *(float4*)(out + (size_t)n0 * OUT + jb) = *(float4*)o;
        }
        if (n1 < N_NODES) {
            float o[4];
            asm("mov.b64 {%0,%1}, %2;" : "=f"(o[0]), "=f"(o[1]) : "l"(acc1[j8 * 2]));
            asm("mov.b64 {%0,%1}, %2;" : "=f"(o[2]), "=f"(o[3]) : "l"(acc1[j8 * 2 + 1]));
            #pragma unroll
            for (int t = 0; t < 4; t++) {
                o[t] += sb[jb + t];
                if (relu) o[t] = fmaxf(o[t], 0.0f);
            }
            *(float4*)(out + (size_t)n1 * OUT + jb) = *(float4*)o;
        }
    }
}

// ---------------- launch ----------------
extern "C" void kernel_launch(void* const* d_in, const int* in_sizes, int n_in,
                              void* d_out, int out_size) {
    const float* x   = (const float*)d_in[0];
    const void*  ei  = d_in[1];
    const float* W1n = (const float*)d_in[2];
    const float* W1s = (const float*)d_in[3];
    const float* b1  = (const float*)d_in[4];
    const float* W2n = (const float*)d_in[5];
    const float* W2s = (const float*)d_in[6];
    const float* b2  = (const float*)d_in[7];
    float* out = (float*)d_out;

    // 0) detect edge_index element width
    detect_kernel<<<1, 1>>>((const int*)ei);

    // 1) zero accumulator + degree
    {
        int n4 = (N_NODES * 64) / 4 + N_NODES / 4;
        zero_sum_deg_kernel<<<(n4 + 255) / 256, 256>>>();
    }

    // 2) layer-1 scatter: sum x[src] into g_sum, count degree
    {
        long long total = (long long)N_EDGES * 16;
        int blocks = (int)((total + 255) / 256);
        scatter_kernel<<<blocks, 256>>>(x, ei, /*use_h=*/0, /*do_deg=*/1);
    }

    // 2b) precompute 1/max(deg,1)
    inv_kernel<<<(N_NODES + 255) / 256, 256>>>();

    // 3) layer-1 transform: g_h = relu(mean@W1n + x@W1s + b1)
    {
        int blocks = (N_NODES + 127) / 128;
        sage_gemm4_kernel<64><<<blocks, 256>>>(x, W1n, W1s, b1, nullptr,
                                               /*feat_is_h=*/0, /*out_is_h=*/1, /*relu=*/1);
    }

    // 4) re-zero accumulator
    {
        int n4 = (N_NODES * 64) / 4;
        zero_sum_kernel<<<(n4 + 255) / 256, 256>>>();
    }

    // 5) layer-2 scatter: sum g_h[src] into g_sum
    {
        long long total = (long long)N_EDGES * 16;
        int blocks = (int)((total + 255) / 256);
        scatter_kernel<<<blocks, 256>>>(nullptr, ei, /*use_h=*/1, /*do_deg=*/0);
    }

    // 6) layer-2 transform: out = mean2@W2n + g_h@W2s + b2
    {
        int blocks = (N_NODES + 127) / 128;
        sage_gemm4_kernel<32><<<blocks, 256>>>(nullptr, W2n, W2s, b2, out,
                                               /*feat_is_h=*/1, /*out_is_h=*/0, /*relu=*/0);
    }
}

// round 5
// speedup vs baseline: 2.2461x; 1.4960x over previous
#include <cuda_runtime.h>
#include <cuda_bf16.h>
#include <cstdint>

#define N_NODES 100000
#define N_EDGES 1600000
#define SCAN_CHUNKS 98            // ceil(100000/1024)

// ---------------- scratch (device globals; no allocations) ----------------
__device__ int   g_cnt[N_NODES];                 // degree histogram
__device__ int   g_part[SCAN_CHUNKS * 1024];     // per-chunk exclusive scan
__device__ int   g_ctot[SCAN_CHUNKS];            // chunk totals
__device__ int   g_coff[SCAN_CHUNKS];            // chunk offsets
__device__ int   g_rowptr[N_NODES + 1];          // CSR row pointers
__device__ int   g_cur[N_NODES];                 // fill cursors
__device__ int   g_col[N_EDGES];                 // CSR column (src) indices
__device__ float g_mean[(size_t)N_NODES * 64];   // aggregated mean (layer 1)
__device__ float g_h[(size_t)N_NODES * 64];      // layer-1 output (relu)
__device__ float g_tu[(size_t)N_NODES * 64];     // [t|u] = h @ [W2n|W2s]
__device__ int   g_is64;                         // edge_index element width flag

// ---------------- dtype width detection for edge_index ----------------
__global__ void detect_kernel(const int* __restrict__ ei32) {
    int odd_nonzero = 0;
    #pragma unroll 8
    for (int i = 0; i < 256; i += 2) {
        if (ei32[i + 1] != 0) odd_nonzero = 1;
    }
    g_is64 = odd_nonzero ? 0 : 1;
}

// ---------------- CSR build ----------------
__global__ void zero_cnt_kernel() {
    int i = blockIdx.x * blockDim.x + threadIdx.x;
    if (i < N_NODES) g_cnt[i] = 0;
}

__global__ void count_kernel(const void* __restrict__ ei, int E) {
    int e = blockIdx.x * blockDim.x + threadIdx.x;
    if (e >= E) return;
    int dst = g_is64 ? (int)((const long long*)ei)[E + e]
                     : ((const int*)ei)[E + e];
    atomicAdd(&g_cnt[dst], 1);
}

__global__ void scan1_kernel() {        // per-chunk exclusive scan, 1024 threads
    __shared__ int s[1024];
    int tid = threadIdx.x;
    int i = blockIdx.x * 1024 + tid;
    int v = (i < N_NODES) ? g_cnt[i] : 0;
    s[tid] = v;
    __syncthreads();
    #pragma unroll
    for (int off = 1; off < 1024; off <<= 1) {
        int t = (tid >= off) ? s[tid - off] : 0;
        __syncthreads();
        s[tid] += t;
        __syncthreads();
    }
    g_part[i] = s[tid] - v;             // exclusive
    if (tid == 1023) g_ctot[blockIdx.x] = s[1023];
}

__global__ void scan2_kernel() {        // scan chunk totals (serial, tiny)
    int acc = 0;
    for (int i = 0; i < SCAN_CHUNKS; i++) { g_coff[i] = acc; acc += g_ctot[i]; }
    g_rowptr[N_NODES] = acc;
}

__global__ void scan3_kernel() {
    int i = blockIdx.x * 1024 + threadIdx.x;
    if (i < N_NODES) {
        int v = g_part[i] + g_coff[blockIdx.x];
        g_rowptr[i] = v;
        g_cur[i] = v;
    }
}

__global__ void fill_kernel(const void* __restrict__ ei, int E) {
    int e = blockIdx.x * blockDim.x + threadIdx.x;
    if (e >= E) return;
    int src, dst;
    if (g_is64) {
        const long long* p = (const long long*)ei;
        src = (int)p[e];
        dst = (int)p[E + e];
    } else {
        const int* p = (const int*)ei;
        src = p[e];
        dst = p[E + e];
    }
    int pos = atomicAdd(&g_cur[dst], 1);
    g_col[pos] = src;
}

// ---------------- CSR gather-mean, 64-wide (layer 1) ----------------
// 16 lanes/node (4 floats each), 16 nodes/block. Atomic-free.
__global__ __launch_bounds__(256)
void agg64_kernel(const float* __restrict__ feat) {
    int tid = threadIdx.x;
    int g = tid >> 4;                   // node in block
    int c = tid & 15;                   // float4 chunk
    int n = blockIdx.x * 16 + g;
    if (n >= N_NODES) return;
    int start = g_rowptr[n], end = g_rowptr[n + 1];
    float4 acc = make_float4(0.f, 0.f, 0.f, 0.f);
    int i = start;
    for (; i + 1 < end; i += 2) {
        int s0 = g_col[i], s1 = g_col[i + 1];
        float4 v0 = *(const float4*)(feat + (size_t)s0 * 64 + c * 4);
        float4 v1 = *(const float4*)(feat + (size_t)s1 * 64 + c * 4);
        acc.x += v0.x + v1.x; acc.y += v0.y + v1.y;
        acc.z += v0.z + v1.z; acc.w += v0.w + v1.w;
    }
    if (i < end) {
        int s0 = g_col[i];
        float4 v0 = *(const float4*)(feat + (size_t)s0 * 64 + c * 4);
        acc.x += v0.x; acc.y += v0.y; acc.z += v0.z; acc.w += v0.w;
    }
    float inv = 1.0f / fmaxf((float)(end - start), 1.0f);
    acc.x *= inv; acc.y *= inv; acc.z *= inv; acc.w *= inv;
    *(float4*)(g_mean + (size_t)n * 64 + c * 4) = acc;
}

// ---------------- CSR gather-mean 32-wide + epilogue (layer 2 output) ----------------
// gathers cols 0..31 (t) of g_tu, out = mean(t) + u + b2.
__global__ __launch_bounds__(256)
void agg_final_kernel(const float* __restrict__ b2, float* __restrict__ out) {
    int tid = threadIdx.x;
    int g = tid >> 3;                   // 32 nodes/block
    int c = tid & 7;
    int n = blockIdx.x * 32 + g;
    if (n >= N_NODES) return;
    int start = g_rowptr[n], end = g_rowptr[n + 1];
    float4 acc = make_float4(0.f, 0.f, 0.f, 0.f);
    int i = start;
    for (; i + 1 < end; i += 2) {
        int s0 = g_col[i], s1 = g_col[i + 1];
        float4 v0 = *(const float4*)(g_tu + (size_t)s0 * 64 + c * 4);
        float4 v1 = *(const float4*)(g_tu + (size_t)s1 * 64 + c * 4);
        acc.x += v0.x + v1.x; acc.y += v0.y + v1.y;
        acc.z += v0.z + v1.z; acc.w += v0.w + v1.w;
    }
    if (i < end) {
        int s0 = g_col[i];
        float4 v0 = *(const float4*)(g_tu + (size_t)s0 * 64 + c * 4);
        acc.x += v0.x; acc.y += v0.y; acc.z += v0.z; acc.w += v0.w;
    }
    float inv = 1.0f / fmaxf((float)(end - start), 1.0f);
    float4 u = *(const float4*)(g_tu + (size_t)n * 64 + 32 + c * 4);
    float4 bb = *(const float4*)(b2 + c * 4);
    float4 o;
    o.x = fmaf(acc.x, inv, u.x + bb.x);
    o.y = fmaf(acc.y, inv, u.y + bb.y);
    o.z = fmaf(acc.z, inv, u.z + bb.z);
    o.w = fmaf(acc.w, inv, u.w + bb.w);
    *(float4*)(out + (size_t)n * 32 + c * 4) = o;
}

// ---------------- pipelined packed-f32x2 GEMMs ----------------
#define FMA2(acc, a2, b2) \
    asm("fma.rn.f32x2 %0, %1, %2, %0;" : "+l"(acc) : "l"(a2), "l"(b2))

// layer-1: h = relu(mean @ W1n + x @ W1s + b1); K=128 virtual, OUT=64.
__global__ __launch_bounds__(256, 3)
void gemmA_kernel(const float* __restrict__ x,
                  const float* __restrict__ Wn, const float* __restrict__ Ws,
                  const float* __restrict__ bias) {
    constexpr int OUT = 64, JB = 4, FP = 33;
    __shared__ float sF[128 * FP];
    __shared__ float sW[32 * OUT];
    __shared__ float sb[OUT];

    int tid = threadIdx.x;
    int base = blockIdx.x * 128;
    int ln = tid >> 2, q = tid & 3;
    int k4 = tid & 7;
    int r_[4], nc_[4];
    #pragma unroll
    for (int it = 0; it < 4; it++) {
        r_[it] = (tid + it * 256) >> 3;
        int n = base + r_[it];
        nc_[it] = (n < N_NODES) ? n : (N_NODES - 1);
    }
    float4 pf[4], pw[2];

    auto load_chunk = [&](int c) {
        const float* srcb = (c < 2) ? g_mean : x;
        int ko = (c & 1) * 32;
        #pragma unroll
        for (int it = 0; it < 4; it++)
            pf[it] = *(const float4*)(srcb + (size_t)nc_[it] * 64 + ko + k4 * 4);
        const float4* wsrc = (const float4*)((c < 2 ? Wn : Ws) + (c & 1) * 32 * OUT);
        pw[0] = wsrc[tid]; pw[1] = wsrc[tid + 256];
    };
    auto store_stage = [&]() {
        #pragma unroll
        for (int it = 0; it < 4; it++) {
            float* d = sF + r_[it] * FP + k4 * 4;
            d[0] = pf[it].x; d[1] = pf[it].y; d[2] = pf[it].z; d[3] = pf[it].w;
        }
        ((float4*)sW)[tid] = pw[0]; ((float4*)sW)[tid + 256] = pw[1];
    };

    load_chunk(0);
    if (tid < OUT) sb[tid] = bias[tid];
    store_stage();
    __syncthreads();

    unsigned long long acc0[JB * 2] = {}, acc1[JB * 2] = {};
    const float* fp0 = sF + ln * FP;
    const float* fp1 = sF + (ln + 64) * FP;
    const float* wq  = sW + (q << 2);

    #pragma unroll 1
    for (int c = 0; c < 4; c++) {
        if (c < 3) load_chunk(c + 1);
        #pragma unroll 8
        for (int kk = 0; kk < 32; kk++) {
            float f0 = fp0[kk], f1 = fp1[kk];
            unsigned long long f0d, f1d;
            asm("mov.b64 %0, {%1,%1};" : "=l"(f0d) : "f"(f0));
            asm("mov.b64 %0, {%1,%1};" : "=l"(f1d) : "f"(f1));
            const float* wr = wq + kk * OUT;
            #pragma unroll
            for (int j8 = 0; j8 < JB; j8++) {
                ulonglong2 w = *(const ulonglong2*)(wr + j8 * 16);
                FMA2(acc0[j8 * 2],     f0d, w.x);
                FMA2(acc0[j8 * 2 + 1], f0d, w.y);
                FMA2(acc1[j8 * 2],     f1d, w.x);
                FMA2(acc1[j8 * 2 + 1], f1d, w.y);
            }
        }
        __syncthreads();
        if (c < 3) { store_stage(); __syncthreads(); }
    }

    int n0 = base + ln, n1 = base + ln + 64;
    #pragma unroll
    for (int j8 = 0; j8 < JB; j8++) {
        int jb = j8 * 16 + (q << 2);
        if (n0 < N_NODES) {
            float o[4];
            asm("mov.b64 {%0,%1}, %2;" : "=f"(o[0]), "=f"(o[1]) : "l"(acc0[j8 * 2]));
            asm("mov.b64 {%0,%1}, %2;" : "=f"(o[2]), "=f"(o[3]) : "l"(acc0[j8 * 2 + 1]));
            #pragma unroll
            for (int t = 0; t < 4; t++) o[t] = fmaxf(o[t] + sb[jb + t], 0.0f);
            *(float4*)(g_h + (size_t)n0 * OUT + jb) = *(float4*)o;
        }
        if (n1 < N_NODES) {
            float o[4];
            asm("mov.b64 {%0,%1}, %2;" : "=f"(o[0]), "=f"(o[1]) : "l"(acc1[j8 * 2]));
            asm("mov.b64 {%0,%1}, %2;" : "=f"(o[2]), "=f"(o[3]) : "l"(acc1[j8 * 2 + 1]));
            #pragma unroll
            for (int t = 0; t < 4; t++) o[t] = fmaxf(o[t] + sb[jb + t], 0.0f);
            *(float4*)(g_h + (size_t)n1 * OUT + jb) = *(float4*)o;
        }
    }
}

// layer-2 pre: [t|u] = h @ [W2n|W2s]; K=64, OUT=64 (cols 0-31 = t, 32-63 = u).
__global__ __launch_bounds__(256, 3)
void gemmD_kernel(const float* __restrict__ Wn, const float* __restrict__ Ws) {
    constexpr int OUT = 64, JB = 4, FP = 33;
    __shared__ float sF[128 * FP];
    __shared__ float sW[32 * OUT];

    int tid = threadIdx.x;
    int base = blockIdx.x * 128;
    int ln = tid >> 2, q = tid & 3;
    int k4 = tid & 7;
    int r_[4], nc_[4];
    #pragma unroll
    for (int it = 0; it < 4; it++) {
        r_[it] = (tid + it * 256) >> 3;
        int n = base + r_[it];
        nc_[it] = (n < N_NODES) ? n : (N_NODES - 1);
    }
    float4 pf[4], pw[2];

    auto load_chunk = [&](int c) {
        #pragma unroll
        for (int it = 0; it < 4; it++)
            pf[it] = *(const float4*)(g_h + (size_t)nc_[it] * 64 + c * 32 + k4 * 4);
        // sW[kk][0:32) = W2n[k][:], sW[kk][32:64) = W2s[k][:]
        #pragma unroll
        for (int iw = 0; iw < 2; iw++) {
            int idx = tid + iw * 256;          // 0..511
            int kk = idx >> 4, jq = idx & 15;
            int k = c * 32 + kk;
            const float* src = (jq < 8) ? (Wn + k * 32 + jq * 4)
                                        : (Ws + k * 32 + (jq - 8) * 4);
            pw[iw] = *(const float4*)src;
        }
    };
    auto store_stage = [&]() {
        #pragma unroll
        for (int it = 0; it < 4; it++) {
            float* d = sF + r_[it] * FP + k4 * 4;
            d[0] = pf[it].x; d[1] = pf[it].y; d[2] = pf[it].z; d[3] = pf[it].w;
        }
        ((float4*)sW)[tid] = pw[0]; ((float4*)sW)[tid + 256] = pw[1];
    };

    load_chunk(0);
    store_stage();
    __syncthreads();

    unsigned long long acc0[JB * 2] = {}, acc1[JB * 2] = {};
    const float* fp0 = sF + ln * FP;
    const float* fp1 = sF + (ln + 64) * FP;
    const float* wq  = sW + (q << 2);

    #pragma unroll 1
    for (int c = 0; c < 2; c++) {
        if (c < 1) load_chunk(c + 1);
        #pragma unroll 8
        for (int kk = 0; kk < 32; kk++) {
            float f0 = fp0[kk], f1 = fp1[kk];
            unsigned long long f0d, f1d;
            asm("mov.b64 %0, {%1,%1};" : "=l"(f0d) : "f"(f0));
            asm("mov.b64 %0, {%1,%1};" : "=l"(f1d) : "f"(f1));
            const float* wr = wq + kk * OUT;
            #pragma unroll
            for (int j8 = 0; j8 < JB; j8++) {
                ulonglong2 w = *(const ulonglong2*)(wr + j8 * 16);
                FMA2(acc0[j8 * 2],     f0d, w.x);
                FMA2(acc0[j8 * 2 + 1], f0d, w.y);
                FMA2(acc1[j8 * 2],     f1d, w.x);
                FMA2(acc1[j8 * 2 + 1], f1d, w.y);
            }
        }
        __syncthreads();
        if (c < 1) { store_stage(); __syncthreads(); }
    }

    int n0 = base + ln, n1 = base + ln + 64;
    #pragma unroll
    for (int j8 = 0; j8 < JB; j8++) {
        int jb = j8 * 16 + (q << 2);
        if (n0 < N_NODES) {
            float o[4];
            asm("mov.b64 {%0,%1}, %2;" : "=f"(o[0]), "=f"(o[1]) : "l"(acc0[j8 * 2]));
            asm("mov.b64 {%0,%1}, %2;" : "=f"(o[2]), "=f"(o[3]) : "l"(acc0[j8 * 2 + 1]));
            *(float4*)(g_tu + (size_t)n0 * OUT + jb) = *(float4*)o;
        }
        if (n1 < N_NODES) {
            float o[4];
            asm("mov.b64 {%0,%1}, %2;" : "=f"(o[0]), "=f"(o[1]) : "l"(acc1[j8 * 2]));
            asm("mov.b64 {%0,%1}, %2;" : "=f"(o[2]), "=f"(o[3]) : "l"(acc1[j8 * 2 + 1]));
            *(float4*)(g_tu + (size_t)n1 * OUT + jb) = *(float4*)o;
        }
    }
}

// ---------------- launch ----------------
extern "C" void kernel_launch(void* const* d_in, const int* in_sizes, int n_in,
                              void* d_out, int out_size) {
    const float* x   = (const float*)d_in[0];
    const void*  ei  = d_in[1];
    const float* W1n = (const float*)d_in[2];
    const float* W1s = (const float*)d_in[3];
    const float* b1  = (const float*)d_in[4];
    const float* W2n = (const float*)d_in[5];
    const float* W2s = (const float*)d_in[6];
    const float* b2  = (const float*)d_in[7];
    float* out = (float*)d_out;
    int E = in_sizes[1] / 2;

    // CSR build
    detect_kernel<<<1, 1>>>((const int*)ei);
    zero_cnt_kernel<<<(N_NODES + 255) / 256, 256>>>();
    count_kernel<<<(E + 255) / 256, 256>>>(ei, E);
    scan1_kernel<<<SCAN_CHUNKS, 1024>>>();
    scan2_kernel<<<1, 1>>>();
    scan3_kernel<<<SCAN_CHUNKS, 1024>>>();
    fill_kernel<<<(E + 255) / 256, 256>>>(ei, E);

    // layer 1
    agg64_kernel<<<(N_NODES + 15) / 16, 256>>>(x);
    gemmA_kernel<<<(N_NODES + 127) / 128, 256>>>(x, W1n, W1s, b1);

    // layer 2
    gemmD_kernel<<<(N_NODES + 127) / 128, 256>>>(W2n, W2s);
    agg_final_kernel<<<(N_NODES + 31) / 32, 256>>>(b2, out);
}

// round 6
// speedup vs baseline: 2.2813x; 1.0156x over previous
#include <cuda_runtime.h>
#include <cuda_bf16.h>
#include <cstdint>

#define N_NODES 100000
#define N_EDGES 1600000
#define SCAN_CHUNKS 98            // ceil(100000/1024)

// ---------------- scratch (device globals; no allocations) ----------------
__device__ int   g_cnt[N_NODES];                 // degree histogram
__device__ int   g_part[SCAN_CHUNKS * 1024];     // per-chunk exclusive scan
__device__ int   g_ctot[SCAN_CHUNKS];            // chunk totals
__device__ int   g_coff[SCAN_CHUNKS];            // chunk offsets
__device__ int   g_rowptr[N_NODES + 1];          // CSR row pointers
__device__ int   g_cur[N_NODES];                 // fill cursors
__device__ int   g_col[N_EDGES];                 // CSR column (src) indices
__device__ float g_mean[(size_t)N_NODES * 64];   // aggregated mean (layer 1)
__device__ float g_h[(size_t)N_NODES * 64];      // layer-1 output (relu)
__device__ float g_tu[(size_t)N_NODES * 64];     // [t|u] = h @ [W2n|W2s]
__device__ int   g_is64;                         // edge_index element width flag

// ---------------- init: zero histogram + dtype width detection ----------------
__global__ void init_kernel(const int* __restrict__ ei32) {
    int i = blockIdx.x * blockDim.x + threadIdx.x;
    if (i < N_NODES) g_cnt[i] = 0;
    if (i == 0) {
        int odd_nonzero = 0;
        #pragma unroll 8
        for (int k = 0; k < 256; k += 2) {
            if (ei32[k + 1] != 0) odd_nonzero = 1;
        }
        g_is64 = odd_nonzero ? 0 : 1;
    }
}

// ---------------- CSR build ----------------
__global__ void count_kernel(const void* __restrict__ ei, int E) {
    int t = blockIdx.x * blockDim.x + threadIdx.x;
    int e0 = t * 2;
    if (e0 >= E) return;
    int is64 = g_is64;
    int d0, d1 = -1;
    if (is64) {
        const long long* p = (const long long*)ei + E;
        d0 = (int)p[e0];
        if (e0 + 1 < E) d1 = (int)p[e0 + 1];
    } else {
        const int* p = (const int*)ei + E;
        d0 = p[e0];
        if (e0 + 1 < E) d1 = p[e0 + 1];
    }
    atomicAdd(&g_cnt[d0], 1);
    if (d1 >= 0) atomicAdd(&g_cnt[d1], 1);
}

__global__ void scan1_kernel() {        // per-chunk exclusive scan, 1024 threads
    __shared__ int s[1024];
    int tid = threadIdx.x;
    int i = blockIdx.x * 1024 + tid;
    int v = (i < N_NODES) ? g_cnt[i] : 0;
    s[tid] = v;
    __syncthreads();
    #pragma unroll
    for (int off = 1; off < 1024; off <<= 1) {
        int t = (tid >= off) ? s[tid - off] : 0;
        __syncthreads();
        s[tid] += t;
        __syncthreads();
    }
    g_part[i] = s[tid] - v;             // exclusive
    if (tid == 1023) g_ctot[blockIdx.x] = s[1023];
}

__global__ void scan2_kernel() {        // parallel scan of 98 chunk totals
    __shared__ int s[128];
    int tid = threadIdx.x;
    int v = (tid < SCAN_CHUNKS) ? g_ctot[tid] : 0;
    s[tid] = v;
    __syncthreads();
    #pragma unroll
    for (int off = 1; off < 128; off <<= 1) {
        int t = (tid >= off) ? s[tid - off] : 0;
        __syncthreads();
        s[tid] += t;
        __syncthreads();
    }
    if (tid < SCAN_CHUNKS) g_coff[tid] = s[tid] - v;   // exclusive
    if (tid == SCAN_CHUNKS - 1) g_rowptr[N_NODES] = s[tid];
}

__global__ void scan3_kernel() {
    int i = blockIdx.x * 1024 + threadIdx.x;
    if (i < N_NODES) {
        int v = g_part[i] + g_coff[blockIdx.x];
        g_rowptr[i] = v;
        g_cur[i] = v;
    }
}

__global__ void fill_kernel(const void* __restrict__ ei, int E) {
    int t = blockIdx.x * blockDim.x + threadIdx.x;
    int e0 = t * 2;
    if (e0 >= E) return;
    int is64 = g_is64;
    int s0, d0, s1 = -1, d1 = -1;
    if (is64) {
        const long long* p = (const long long*)ei;
        s0 = (int)p[e0]; d0 = (int)p[E + e0];
        if (e0 + 1 < E) { s1 = (int)p[e0 + 1]; d1 = (int)p[E + e0 + 1]; }
    } else {
        const int* p = (const int*)ei;
        s0 = p[e0]; d0 = p[E + e0];
        if (e0 + 1 < E) { s1 = p[e0 + 1]; d1 = p[E + e0 + 1]; }
    }
    int p0 = atomicAdd(&g_cur[d0], 1);
    g_col[p0] = s0;
    if (d1 >= 0) {
        int p1 = atomicAdd(&g_cur[d1], 1);
        g_col[p1] = s1;
    }
}

// ---------------- CSR gather-mean, 64-wide (layer 1), MLP=4 ----------------
__global__ __launch_bounds__(256)
void agg64_kernel(const float* __restrict__ feat) {
    int tid = threadIdx.x;
    int g = tid >> 4;                   // node in block
    int c = tid & 15;                   // float4 chunk
    int n = blockIdx.x * 16 + g;
    if (n >= N_NODES) return;
    int start = g_rowptr[n], end = g_rowptr[n + 1];
    float4 acc = make_float4(0.f, 0.f, 0.f, 0.f);
    int i = start;
    for (; i + 3 < end; i += 4) {
        int s0 = g_col[i], s1 = g_col[i + 1], s2 = g_col[i + 2], s3 = g_col[i + 3];
        float4 v0 = *(const float4*)(feat + (size_t)s0 * 64 + c * 4);
        float4 v1 = *(const float4*)(feat + (size_t)s1 * 64 + c * 4);
        float4 v2 = *(const float4*)(feat + (size_t)s2 * 64 + c * 4);
        float4 v3 = *(const float4*)(feat + (size_t)s3 * 64 + c * 4);
        acc.x += (v0.x + v1.x) + (v2.x + v3.x);
        acc.y += (v0.y + v1.y) + (v2.y + v3.y);
        acc.z += (v0.z + v1.z) + (v2.z + v3.z);
        acc.w += (v0.w + v1.w) + (v2.w + v3.w);
    }
    for (; i < end; i++) {
        int s0 = g_col[i];
        float4 v0 = *(const float4*)(feat + (size_t)s0 * 64 + c * 4);
        acc.x += v0.x; acc.y += v0.y; acc.z += v0.z; acc.w += v0.w;
    }
    float inv = 1.0f / fmaxf((float)(end - start), 1.0f);
    acc.x *= inv; acc.y *= inv; acc.z *= inv; acc.w *= inv;
    *(float4*)(g_mean + (size_t)n * 64 + c * 4) = acc;
}

// ---------------- CSR gather-mean 32-wide + epilogue (layer 2 output), MLP=4 ----------------
__global__ __launch_bounds__(256)
void agg_final_kernel(const float* __restrict__ b2, float* __restrict__ out) {
    int tid = threadIdx.x;
    int g = tid >> 3;                   // 32 nodes/block
    int c = tid & 7;
    int n = blockIdx.x * 32 + g;
    if (n >= N_NODES) return;
    int start = g_rowptr[n], end = g_rowptr[n + 1];
    float4 acc = make_float4(0.f, 0.f, 0.f, 0.f);
    int i = start;
    for (; i + 3 < end; i += 4) {
        int s0 = g_col[i], s1 = g_col[i + 1], s2 = g_col[i + 2], s3 = g_col[i + 3];
        float4 v0 = *(const float4*)(g_tu + (size_t)s0 * 64 + c * 4);
        float4 v1 = *(const float4*)(g_tu + (size_t)s1 * 64 + c * 4);
        float4 v2 = *(const float4*)(g_tu + (size_t)s2 * 64 + c * 4);
        float4 v3 = *(const float4*)(g_tu + (size_t)s3 * 64 + c * 4);
        acc.x += (v0.x + v1.x) + (v2.x + v3.x);
        acc.y += (v0.y + v1.y) + (v2.y + v3.y);
        acc.z += (v0.z + v1.z) + (v2.z + v3.z);
        acc.w += (v0.w + v1.w) + (v2.w + v3.w);
    }
    for (; i < end; i++) {
        int s0 = g_col[i];
        float4 v0 = *(const float4*)(g_tu + (size_t)s0 * 64 + c * 4);
        acc.x += v0.x; acc.y += v0.y; acc.z += v0.z; acc.w += v0.w;
    }
    float inv = 1.0f / fmaxf((float)(end - start), 1.0f);
    float4 u = *(const float4*)(g_tu + (size_t)n * 64 + 32 + c * 4);
    float4 bb = *(const float4*)(b2 + c * 4);
    float4 o;
    o.x = fmaf(acc.x, inv, u.x + bb.x);
    o.y = fmaf(acc.y, inv, u.y + bb.y);
    o.z = fmaf(acc.z, inv, u.z + bb.z);
    o.w = fmaf(acc.w, inv, u.w + bb.w);
    *(float4*)(out + (size_t)n * 32 + c * 4) = o;
}

// ---------------- pipelined packed-f32x2 GEMMs ----------------
#define FMA2(acc, a2, b2) \
    asm("fma.rn.f32x2 %0, %1, %2, %0;" : "+l"(acc) : "l"(a2), "l"(b2))

// layer-1: h = relu(mean @ W1n + x @ W1s + b1); K=128 virtual, OUT=64.
__global__ __launch_bounds__(256, 3)
void gemmA_kernel(const float* __restrict__ x,
                  const float* __restrict__ Wn, const float* __restrict__ Ws,
                  const float* __restrict__ bias) {
    constexpr int OUT = 64, JB = 4, FP = 33;
    __shared__ float sF[128 * FP];
    __shared__ float sW[32 * OUT];
    __shared__ float sb[OUT];

    int tid = threadIdx.x;
    int base = blockIdx.x * 128;
    int ln = tid >> 2, q = tid & 3;
    int k4 = tid & 7;
    int r_[4], nc_[4];
    #pragma unroll
    for (int it = 0; it < 4; it++) {
        r_[it] = (tid + it * 256) >> 3;
        int n = base + r_[it];
        nc_[it] = (n < N_NODES) ? n : (N_NODES - 1);
    }
    float4 pf[4], pw[2];

    auto load_chunk = [&](int c) {
        const float* srcb = (c < 2) ? g_mean : x;
        int ko = (c & 1) * 32;
        #pragma unroll
        for (int it = 0; it < 4; it++)
            pf[it] = *(const float4*)(srcb + (size_t)nc_[it] * 64 + ko + k4 * 4);
        const float4* wsrc = (const float4*)((c < 2 ? Wn : Ws) + (c & 1) * 32 * OUT);
        pw[0] = wsrc[tid]; pw[1] = wsrc[tid + 256];
    };
    auto store_stage = [&]() {
        #pragma unroll
        for (int it = 0; it < 4; it++) {
            float* d = sF + r_[it] * FP + k4 * 4;
            d[0] = pf[it].x; d[1] = pf[it].y; d[2] = pf[it].z; d[3] = pf[it].w;
        }
        ((float4*)sW)[tid] = pw[0]; ((float4*)sW)[tid + 256] = pw[1];
    };

    load_chunk(0);
    if (tid < OUT) sb[tid] = bias[tid];
    store_stage();
    __syncthreads();

    unsigned long long acc0[JB * 2] = {}, acc1[JB * 2] = {};
    const float* fp0 = sF + ln * FP;
    const float* fp1 = sF + (ln + 64) * FP;
    const float* wq  = sW + (q << 2);

    #pragma unroll 1
    for (int c = 0; c < 4; c++) {
        if (c < 3) load_chunk(c + 1);
        #pragma unroll 8
        for (int kk = 0; kk < 32; kk++) {
            float f0 = fp0[kk], f1 = fp1[kk];
            unsigned long long f0d, f1d;
            asm("mov.b64 %0, {%1,%1};" : "=l"(f0d) : "f"(f0));
            asm("mov.b64 %0, {%1,%1};" : "=l"(f1d) : "f"(f1));
            const float* wr = wq + kk * OUT;
            #pragma unroll
            for (int j8 = 0; j8 < JB; j8++) {
                ulonglong2 w = *(const ulonglong2*)(wr + j8 * 16);
                FMA2(acc0[j8 * 2],     f0d, w.x);
                FMA2(acc0[j8 * 2 + 1], f0d, w.y);
                FMA2(acc1[j8 * 2],     f1d, w.x);
                FMA2(acc1[j8 * 2 + 1], f1d, w.y);
            }
        }
        __syncthreads();
        if (c < 3) { store_stage(); __syncthreads(); }
    }

    int n0 = base + ln, n1 = base + ln + 64;
    #pragma unroll
    for (int j8 = 0; j8 < JB; j8++) {
        int jb = j8 * 16 + (q << 2);
        if (n0 < N_NODES) {
            float o[4];
            asm("mov.b64 {%0,%1}, %2;" : "=f"(o[0]), "=f"(o[1]) : "l"(acc0[j8 * 2]));
            asm("mov.b64 {%0,%1}, %2;" : "=f"(o[2]), "=f"(o[3]) : "l"(acc0[j8 * 2 + 1]));
            #pragma unroll
            for (int t = 0; t < 4; t++) o[t] = fmaxf(o[t] + sb[jb + t], 0.0f);
            *(float4*)(g_h + (size_t)n0 * OUT + jb) = *(float4*)o;
        }
        if (n1 < N_NODES) {
            float o[4];
            asm("mov.b64 {%0,%1}, %2;" : "=f"(o[0]), "=f"(o[1]) : "l"(acc1[j8 * 2]));
            asm("mov.b64 {%0,%1}, %2;" : "=f"(o[2]), "=f"(o[3]) : "l"(acc1[j8 * 2 + 1]));
            #pragma unroll
            for (int t = 0; t < 4; t++) o[t] = fmaxf(o[t] + sb[jb + t], 0.0f);
            *(float4*)(g_h + (size_t)n1 * OUT + jb) = *(float4*)o;
        }
    }
}

// layer-2 pre: [t|u] = h @ [W2n|W2s]; K=64, OUT=64 (cols 0-31 = t, 32-63 = u).
__global__ __launch_bounds__(256, 3)
void gemmD_kernel(const float* __restrict__ Wn, const float* __restrict__ Ws) {
    constexpr int OUT = 64, JB = 4, FP = 33;
    __shared__ float sF[128 * FP];
    __shared__ float sW[32 * OUT];

    int tid = threadIdx.x;
    int base = blockIdx.x * 128;
    int ln = tid >> 2, q = tid & 3;
    int k4 = tid & 7;
    int r_[4], nc_[4];
    #pragma unroll
    for (int it = 0; it < 4; it++) {
        r_[it] = (tid + it * 256) >> 3;
        int n = base + r_[it];
        nc_[it] = (n < N_NODES) ? n : (N_NODES - 1);
    }
    float4 pf[4], pw[2];

    auto load_chunk = [&](int c) {
        #pragma unroll
        for (int it = 0; it < 4; it++)
            pf[it] = *(const float4*)(g_h + (size_t)nc_[it] * 64 + c * 32 + k4 * 4);
        #pragma unroll
        for (int iw = 0; iw < 2; iw++) {
            int idx = tid + iw * 256;          // 0..511
            int kk = idx >> 4, jq = idx & 15;
            int k = c * 32 + kk;
            const float* src = (jq < 8) ? (Wn + k * 32 + jq * 4)
                                        : (Ws + k * 32 + (jq - 8) * 4);
            pw[iw] = *(const float4*)src;
        }
    };
    auto store_stage = [&]() {
        #pragma unroll
        for (int it = 0; it < 4; it++) {
            float* d = sF + r_[it] * FP + k4 * 4;
            d[0] = pf[it].x; d[1] = pf[it].y; d[2] = pf[it].z; d[3] = pf[it].w;
        }
        ((float4*)sW)[tid] = pw[0]; ((float4*)sW)[tid + 256] = pw[1];
    };

    load_chunk(0);
    store_stage();
    __syncthreads();

    unsigned long long acc0[JB * 2] = {}, acc1[JB * 2] = {};
    const float* fp0 = sF + ln * FP;
    const float* fp1 = sF + (ln + 64) * FP;
    const float* wq  = sW + (q << 2);

    #pragma unroll 1
    for (int c = 0; c < 2; c++) {
        if (c < 1) load_chunk(c + 1);
        #pragma unroll 8
        for (int kk = 0; kk < 32; kk++) {
            float f0 = fp0[kk], f1 = fp1[kk];
            unsigned long long f0d, f1d;
            asm("mov.b64 %0, {%1,%1};" : "=l"(f0d) : "f"(f0));
            asm("mov.b64 %0, {%1,%1};" : "=l"(f1d) : "f"(f1));
            const float* wr = wq + kk * OUT;
            #pragma unroll
            for (int j8 = 0; j8 < JB; j8++) {
                ulonglong2 w = *(const ulonglong2*)(wr + j8 * 16);
                FMA2(acc0[j8 * 2],     f0d, w.x);
                FMA2(acc0[j8 * 2 + 1], f0d, w.y);
                FMA2(acc1[j8 * 2],     f1d, w.x);
                FMA2(acc1[j8 * 2 + 1], f1d, w.y);
            }
        }
        __syncthreads();
        if (c < 1) { store_stage(); __syncthreads(); }
    }

    int n0 = base + ln, n1 = base + ln + 64;
    #pragma unroll
    for (int j8 = 0; j8 < JB; j8++) {
        int jb = j8 * 16 + (q << 2);
        if (n0 < N_NODES) {
            float o[4];
            asm("mov.b64 {%0,%1}, %2;" : "=f"(o[0]), "=f"(o[1]) : "l"(acc0[j8 * 2]));
            asm("mov.b64 {%0,%1}, %2;" : "=f"(o[2]), "=f"(o[3]) : "l"(acc0[j8 * 2 + 1]));
            *(float4*)(g_tu + (size_t)n0 * OUT + jb) = *(float4*)o;
        }
        if (n1 < N_NODES) {
            float o[4];
            asm("mov.b64 {%0,%1}, %2;" : "=f"(o[0]), "=f"(o[1]) : "l"(acc1[j8 * 2]));
            asm("mov.b64 {%0,%1}, %2;" : "=f"(o[2]), "=f"(o[3]) : "l"(acc1[j8 * 2 + 1]));
            *(float4*)(g_tu + (size_t)n1 * OUT + jb) = *(float4*)o;
        }
    }
}

// ---------------- launch ----------------
extern "C" void kernel_launch(void* const* d_in, const int* in_sizes, int n_in,
                              void* d_out, int out_size) {
    const float* x   = (const float*)d_in[0];
    const void*  ei  = d_in[1];
    const float* W1n = (const float*)d_in[2];
    const float* W1s = (const float*)d_in[3];
    const float* b1  = (const float*)d_in[4];
    const float* W2n = (const float*)d_in[5];
    const float* W2s = (const float*)d_in[6];
    const float* b2  = (const float*)d_in[7];
    float* out = (float*)d_out;
    int E = in_sizes[1] / 2;

    // CSR build
    init_kernel<<<(N_NODES + 255) / 256, 256>>>((const int*)ei);
    count_kernel<<<(E / 2 + 256) / 256, 256>>>(ei, E);
    scan1_kernel<<<SCAN_CHUNKS, 1024>>>();
    scan2_kernel<<<1, 128>>>();
    scan3_kernel<<<SCAN_CHUNKS, 1024>>>();
    fill_kernel<<<(E / 2 + 256) / 256, 256>>>(ei, E);

    // layer 1
    agg64_kernel<<<(N_NODES + 15) / 16, 256>>>(x);
    gemmA_kernel<<<(N_NODES + 127) / 128, 256>>>(x, W1n, W1s, b1);

    // layer 2
    gemmD_kernel<<<(N_NODES + 127) / 128, 256>>>(W2n, W2s);
    agg_final_kernel<<<(N_NODES + 31) / 32, 256>>>(b2, out);
}

// round 8
// speedup vs baseline: 2.4181x; 1.0600x over previous
#include <cuda_runtime.h>
#include <cuda_bf16.h>
#include <cstdint>

#define N_NODES 100000
#define N_EDGES 1600000
#define SCAN_CHUNKS 98            // ceil(100000/1024)

// ---------------- scratch (device globals; no allocations) ----------------
// g_cnt is zero at process start (static zero-init) and re-zeroed by each
// fill_kernel call for the next invocation (same work every call).
__device__ int   g_cnt[N_NODES];                 // degree histogram
__device__ int   g_part[SCAN_CHUNKS * 1024];     // per-chunk exclusive scan
__device__ int   g_ctot[SCAN_CHUNKS];            // chunk totals
__device__ int   g_rowptr[N_NODES + 1];          // CSR row pointers
__device__ int   g_cur[N_NODES];                 // fill cursors
__device__ int   g_col[N_EDGES];                 // CSR column (src) indices
__device__ float g_t1[(size_t)N_NODES * 64];     // x @ W1n
__device__ float g_u1[(size_t)N_NODES * 64];     // x @ W1s
__device__ float g_h [(size_t)N_NODES * 64];     // layer-1 output (relu)
__device__ float g_t2[(size_t)N_NODES * 32];     // h @ W2n
__device__ float g_u2[(size_t)N_NODES * 32];     // h @ W2s

// inline edge-width detection: int64 values < 2^31 have zero high words.
__device__ __forceinline__ int detect_is64(const int* ei32) {
    return (ei32[1] == 0 && ei32[3] == 0 && ei32[5] == 0 && ei32[7] == 0) ? 1 : 0;
}

// ---------------- CSR build ----------------
__global__ void count_kernel(const void* __restrict__ ei, int E) {
    int t = blockIdx.x * blockDim.x + threadIdx.x;
    int e0 = t * 2;
    if (e0 >= E) return;
    int is64 = detect_is64((const int*)ei);
    int d0, d1 = -1;
    if (is64) {
        const long long* p = (const long long*)ei + E;
        d0 = (int)p[e0];
        if (e0 + 1 < E) d1 = (int)p[e0 + 1];
    } else {
        const int* p = (const int*)ei + E;
        d0 = p[e0];
        if (e0 + 1 < E) d1 = p[e0 + 1];
    }
    atomicAdd(&g_cnt[d0], 1);
    if (d1 >= 0) atomicAdd(&g_cnt[d1], 1);
}

__global__ void scan1_kernel() {        // per-chunk exclusive scan, 1024 threads
    __shared__ int s[1024];
    int tid = threadIdx.x;
    int i = blockIdx.x * 1024 + tid;
    int v = (i < N_NODES) ? g_cnt[i] : 0;
    s[tid] = v;
    __syncthreads();
    #pragma unroll
    for (int off = 1; off < 1024; off <<= 1) {
        int t = (tid >= off) ? s[tid - off] : 0;
        __syncthreads();
        s[tid] += t;
        __syncthreads();
    }
    g_part[i] = s[tid] - v;             // exclusive
    if (tid == 1023) g_ctot[blockIdx.x] = s[1023];
}

__global__ void scan3_kernel() {        // adds chunk offsets (each block scans totals)
    __shared__ int s[128];
    int tid = threadIdx.x;
    if (tid < 128) {
        int v = (tid < SCAN_CHUNKS) ? g_ctot[tid] : 0;
        s[tid] = v;
    }
    __syncthreads();
    #pragma unroll
    for (int off = 1; off < 128; off <<= 1) {
        int t = (tid < 128 && tid >= off) ? s[tid - off] : 0;
        __syncthreads();
        if (tid < 128) s[tid] += t;
        __syncthreads();
    }
    // s[c] = inclusive total through chunk c
    int coff = (blockIdx.x == 0) ? 0 : s[blockIdx.x - 1];
    int i = blockIdx.x * 1024 + tid;
    if (i < N_NODES) {
        int v = g_part[i] + coff;
        g_rowptr[i] = v;
        g_cur[i] = v;
    }
    if (blockIdx.x == 0 && tid == 0) g_rowptr[N_NODES] = s[SCAN_CHUNKS - 1];
}

__global__ void fill_kernel(const void* __restrict__ ei, int E) {
    int t = blockIdx.x * blockDim.x + threadIdx.x;
    // re-zero histogram for the next invocation (g_cnt free after scan1)
    if (t < N_NODES / 4) ((int4*)g_cnt)[t] = make_int4(0, 0, 0, 0);
    int e0 = t * 2;
    if (e0 >= E) return;
    int is64 = detect_is64((const int*)ei);
    int s0, d0, s1 = -1, d1 = -1;
    if (is64) {
        const long long* p = (const long long*)ei;
        s0 = (int)p[e0]; d0 = (int)p[E + e0];
        if (e0 + 1 < E) { s1 = (int)p[e0 + 1]; d1 = (int)p[E + e0 + 1]; }
    } else {
        const int* p = (const int*)ei;
        s0 = p[e0]; d0 = p[E + e0];
        if (e0 + 1 < E) { s1 = p[e0 + 1]; d1 = p[E + e0 + 1]; }
    }
    int p0 = atomicAdd(&g_cur[d0], 1);
    g_col[p0] = s0;
    if (d1 >= 0) {
        int p1 = atomicAdd(&g_cur[d1], 1);
        g_col[p1] = s1;
    }
}

// ---------------- pipelined packed-f32x2 dual-output GEMM ----------------
// [tA|uB] = src @ [Wa|Wb], src rows 64 wide, each output OUTT wide.
// LAYER selects device-global src/dst INSIDE device code (host cannot pass
// __device__ symbols as kernel args — that was the round-7 bug).
#define FMA2(acc, a2, b2) \
    asm("fma.rn.f32x2 %0, %1, %2, %0;" : "+l"(acc) : "l"(a2), "l"(b2))

template<int OUTT, int LAYER>
__global__ __launch_bounds__(256, 2)
void gemm_dual_kernel(const float* __restrict__ xsrc,
                      const float* __restrict__ Wa,   // [64, OUTT]
                      const float* __restrict__ Wb) { // [64, OUTT]
    constexpr int OUT = 2 * OUTT;          // 128 or 64
    constexpr int TPN = OUT / 16;          // 8 or 4 threads per node
    constexpr int NB  = 8192 / OUT;        // 64 or 128 nodes per block
    constexpr int HALF = NB / 2;
    constexpr int FP  = 33;
    constexpr int NF4 = NB / 32;           // feature float4 per thread (2 or 4)
    constexpr int NW4 = OUT / 32;          // weight float4 per thread (4 or 2)
    constexpr int JQW = OUT / 4;           // float4 per weight row

    const float* src = (LAYER == 1) ? xsrc : g_h;
    float* dstA = (LAYER == 1) ? g_t1 : g_t2;
    float* dstB = (LAYER == 1) ? g_u1 : g_u2;

    __shared__ float sF[NB * FP];
    __shared__ float sW[32 * OUT];

    int tid = threadIdx.x;
    int base = blockIdx.x * NB;
    int ln = tid / TPN;
    int q  = tid % TPN;
    int k4 = tid & 7;

    int r_[NF4], nc_[NF4];
    #pragma unroll
    for (int it = 0; it < NF4; it++) {
        r_[it] = (tid + it * 256) >> 3;
        int n = base + r_[it];
        nc_[it] = (n < N_NODES) ? n : (N_NODES - 1);
    }
    float4 pf[NF4], pw[NW4];

    auto load_chunk = [&](int c) {
        #pragma unroll
        for (int it = 0; it < NF4; it++)
            pf[it] = *(const float4*)(src + (size_t)nc_[it] * 64 + c * 32 + k4 * 4);
        #pragma unroll
        for (int iw = 0; iw < NW4; iw++) {
            int idx = tid + iw * 256;
            int kk = idx / JQW, jq = idx % JQW;
            int k = c * 32 + kk;
            const float* wsrc = (jq < OUTT / 4) ? (Wa + k * OUTT + jq * 4)
                                                : (Wb + k * OUTT + jq * 4 - OUTT);
            pw[iw] = *(const float4*)wsrc;
        }
    };
    auto store_stage = [&]() {
        #pragma unroll
        for (int it = 0; it < NF4; it++) {
            float* d = sF + r_[it] * FP + k4 * 4;
            d[0] = pf[it].x; d[1] = pf[it].y; d[2] = pf[it].z; d[3] = pf[it].w;
        }
        #pragma unroll
        for (int iw = 0; iw < NW4; iw++)
            ((float4*)sW)[tid + iw * 256] = pw[iw];
    };

    load_chunk(0);
    store_stage();
    __syncthreads();

    unsigned long long acc0[8] = {}, acc1[8] = {};
    const float* fp0 = sF + ln * FP;
    const float* fp1 = sF + (ln + HALF) * FP;
    const float* wq  = sW + (q << 2);

    #pragma unroll 1
    for (int c = 0; c < 2; c++) {
        if (c < 1) load_chunk(1);
        #pragma unroll 8
        for (int kk = 0; kk < 32; kk++) {
            float f0 = fp0[kk], f1 = fp1[kk];
            unsigned long long f0d, f1d;
            asm("mov.b64 %0, {%1,%1};" : "=l"(f0d) : "f"(f0));
            asm("mov.b64 %0, {%1,%1};" : "=l"(f1d) : "f"(f1));
            const float* wr = wq + kk * OUT;
            #pragma unroll
            for (int j8 = 0; j8 < 4; j8++) {
                ulonglong2 w = *(const ulonglong2*)(wr + j8 * TPN * 4);
                FMA2(acc0[j8 * 2],     f0d, w.x);
                FMA2(acc0[j8 * 2 + 1], f0d, w.y);
                FMA2(acc1[j8 * 2],     f1d, w.x);
                FMA2(acc1[j8 * 2 + 1], f1d, w.y);
            }
        }
        __syncthreads();
        if (c < 1) { store_stage(); __syncthreads(); }
    }

    int n0 = base + ln, n1 = base + ln + HALF;
    #pragma unroll
    for (int j8 = 0; j8 < 4; j8++) {
        int jb = j8 * TPN * 4 + (q << 2);
        float* dst = (j8 < 2) ? dstA : dstB;
        int joff = (j8 < 2) ? jb : jb - OUTT;
        if (n0 < N_NODES) {
            float o[4];
            asm("mov.b64 {%0,%1}, %2;" : "=f"(o[0]), "=f"(o[1]) : "l"(acc0[j8 * 2]));
            asm("mov.b64 {%0,%1}, %2;" : "=f"(o[2]), "=f"(o[3]) : "l"(acc0[j8 * 2 + 1]));
            *(float4*)(dst + (size_t)n0 * OUTT + joff) = *(float4*)o;
        }
        if (n1 < N_NODES) {
            float o[4];
            asm("mov.b64 {%0,%1}, %2;" : "=f"(o[0]), "=f"(o[1]) : "l"(acc1[j8 * 2]));
            asm("mov.b64 {%0,%1}, %2;" : "=f"(o[2]), "=f"(o[3]) : "l"(acc1[j8 * 2 + 1]));
            *(float4*)(dst + (size_t)n1 * OUTT + joff) = *(float4*)o;
        }
    }
}

// ---------------- gather-mean + epilogue kernels ----------------
// layer 1: h = relu(mean_gather(t1) + u1 + b1); rows 64 wide; 16 lanes/node.
__global__ __launch_bounds__(256)
void aggH_kernel(const float* __restrict__ b1) {
    int tid = threadIdx.x;
    int g = tid >> 4;
    int c = tid & 15;
    int n = blockIdx.x * 16 + g;
    if (n >= N_NODES) return;
    int start = g_rowptr[n], end = g_rowptr[n + 1];
    float4 acc = make_float4(0.f, 0.f, 0.f, 0.f);
    int i = start;
    for (; i + 3 < end; i += 4) {
        int s0 = g_col[i], s1 = g_col[i + 1], s2 = g_col[i + 2], s3 = g_col[i + 3];
        float4 v0 = *(const float4*)(g_t1 + (size_t)s0 * 64 + c * 4);
        float4 v1 = *(const float4*)(g_t1 + (size_t)s1 * 64 + c * 4);
        float4 v2 = *(const float4*)(g_t1 + (size_t)s2 * 64 + c * 4);
        float4 v3 = *(const float4*)(g_t1 + (size_t)s3 * 64 + c * 4);
        acc.x += (v0.x + v1.x) + (v2.x + v3.x);
        acc.y += (v0.y + v1.y) + (v2.y + v3.y);
        acc.z += (v0.z + v1.z) + (v2.z + v3.z);
        acc.w += (v0.w + v1.w) + (v2.w + v3.w);
    }
    for (; i < end; i++) {
        int s0 = g_col[i];
        float4 v0 = *(const float4*)(g_t1 + (size_t)s0 * 64 + c * 4);
        acc.x += v0.x; acc.y += v0.y; acc.z += v0.z; acc.w += v0.w;
    }
    float inv = 1.0f / fmaxf((float)(end - start), 1.0f);
    float4 u = *(const float4*)(g_u1 + (size_t)n * 64 + c * 4);
    float4 bb = *(const float4*)(b1 + c * 4);
    float4 o;
    o.x = fmaxf(fmaf(acc.x, inv, u.x + bb.x), 0.0f);
    o.y = fmaxf(fmaf(acc.y, inv, u.y + bb.y), 0.0f);
    o.z = fmaxf(fmaf(acc.z, inv, u.z + bb.z), 0.0f);
    o.w = fmaxf(fmaf(acc.w, inv, u.w + bb.w), 0.0f);
    *(float4*)(g_h + (size_t)n * 64 + c * 4) = o;
}

// layer 2: out = mean_gather(t2) + u2 + b2; rows 32 wide; 8 lanes/node.
__global__ __launch_bounds__(256)
void agg_final_kernel(const float* __restrict__ b2, float* __restrict__ out) {
    int tid = threadIdx.x;
    int g = tid >> 3;
    int c = tid & 7;
    int n = blockIdx.x * 32 + g;
    if (n >= N_NODES) return;
    int start = g_rowptr[n], end = g_rowptr[n + 1];
    float4 acc = make_float4(0.f, 0.f, 0.f, 0.f);
    int i = start;
    for (; i + 3 < end; i += 4) {
        int s0 = g_col[i], s1 = g_col[i + 1], s2 = g_col[i + 2], s3 = g_col[i + 3];
        float4 v0 = *(const float4*)(g_t2 + (size_t)s0 * 32 + c * 4);
        float4 v1 = *(const float4*)(g_t2 + (size_t)s1 * 32 + c * 4);
        float4 v2 = *(const float4*)(g_t2 + (size_t)s2 * 32 + c * 4);
        float4 v3 = *(const float4*)(g_t2 + (size_t)s3 * 32 + c * 4);
        acc.x += (v0.x + v1.x) + (v2.x + v3.x);
        acc.y += (v0.y + v1.y) + (v2.y + v3.y);
        acc.z += (v0.z + v1.z) + (v2.z + v3.z);
        acc.w += (v0.w + v1.w) + (v2.w + v3.w);
    }
    for (; i < end; i++) {
        int s0 = g_col[i];
        float4 v0 = *(const float4*)(g_t2 + (size_t)s0 * 32 + c * 4);
        acc.x += v0.x; acc.y += v0.y; acc.z += v0.z; acc.w += v0.w;
    }
    float inv = 1.0f / fmaxf((float)(end - start), 1.0f);
    float4 u = *(const float4*)(g_u2 + (size_t)n * 32 + c * 4);
    float4 bb = *(const float4*)(b2 + c * 4);
    float4 o;
    o.x = fmaf(acc.x, inv, u.x + bb.x);
    o.y = fmaf(acc.y, inv, u.y + bb.y);
    o.z = fmaf(acc.z, inv, u.z + bb.z);
    o.w = fmaf(acc.w, inv, u.w + bb.w);
    *(float4*)(out + (size_t)n * 32 + c * 4) = o;
}

// ---------------- launch ----------------
extern "C" void kernel_launch(void* const* d_in, const int* in_sizes, int n_in,
                              void* d_out, int out_size) {
    const float* x   = (const float*)d_in[0];
    const void*  ei  = d_in[1];
    const float* W1n = (const float*)d_in[2];
    const float* W1s = (const float*)d_in[3];
    const float* b1  = (const float*)d_in[4];
    const float* W2n = (const float*)d_in[5];
    const float* W2s = (const float*)d_in[6];
    const float* b2  = (const float*)d_in[7];
    float* out = (float*)d_out;
    int E = in_sizes[1] / 2;

    // CSR build (4 launches)
    count_kernel<<<(E / 2 + 256) / 256, 256>>>(ei, E);
    scan1_kernel<<<SCAN_CHUNKS, 1024>>>();
    scan3_kernel<<<SCAN_CHUNKS, 1024>>>();
    fill_kernel<<<(E / 2 + 256) / 256, 256>>>(ei, E);

    // layer 1: [t1|u1] = x @ [W1n|W1s]; h = relu(mean(t1) + u1 + b1)
    gemm_dual_kernel<64, 1><<<(N_NODES + 63) / 64, 256>>>(x, W1n, W1s);
    aggH_kernel<<<(N_NODES + 15) / 16, 256>>>(b1);

    // layer 2: [t2|u2] = h @ [W2n|W2s]; out = mean(t2) + u2 + b2
    gemm_dual_kernel<32, 2><<<(N_NODES + 127) / 128, 256>>>(nullptr, W2n, W2s);
    agg_final_kernel<<<(N_NODES + 31) / 32, 256>>>(b2, out);
}

// round 9
// speedup vs baseline: 2.5326x; 1.0474x over previous
#include <cuda_runtime.h>
#include <cuda_bf16.h>
#include <cstdint>

#define N_NODES 100000
#define N_EDGES 1600000
#define SCAN_CHUNKS 98            // ceil(100000/1024)

// ---------------- scratch (device globals; no allocations) ----------------
// g_cnt is zero at process start (static zero-init) and re-zeroed by each
// fill_kernel call for the next invocation (same work every call).
__device__ int   g_cnt[N_NODES];                 // degree histogram
__device__ int   g_rank[N_EDGES];                // per-edge rank within its dst
__device__ int   g_part[SCAN_CHUNKS * 1024];     // per-chunk exclusive scan
__device__ int   g_ctot[SCAN_CHUNKS];            // chunk totals
__device__ int   g_rowptr[N_NODES + 1];          // CSR row pointers
__device__ int   g_col[N_EDGES];                 // CSR column (src) indices
__device__ float g_t1[(size_t)N_NODES * 64];     // x @ W1n
__device__ float g_u1[(size_t)N_NODES * 64];     // x @ W1s
__device__ float g_h [(size_t)N_NODES * 64];     // layer-1 output (relu)
__device__ float g_t2[(size_t)N_NODES * 32];     // h @ W2n
__device__ float g_u2[(size_t)N_NODES * 32];     // h @ W2s

// inline edge-width detection: int64 values < 2^31 have zero high words.
__device__ __forceinline__ int detect_is64(const int* ei32) {
    return (ei32[1] == 0 && ei32[3] == 0 && ei32[5] == 0 && ei32[7] == 0) ? 1 : 0;
}

// ---------------- CSR build ----------------
// count: histogram + record each edge's rank within its destination.
__global__ void count_kernel(const void* __restrict__ ei, int E) {
    int t = blockIdx.x * blockDim.x + threadIdx.x;
    int e0 = t * 2;
    if (e0 >= E) return;
    int is64 = detect_is64((const int*)ei);
    int d0, d1 = -1;
    if (is64) {
        const long long* p = (const long long*)ei + E;
        d0 = (int)p[e0];
        if (e0 + 1 < E) d1 = (int)p[e0 + 1];
    } else {
        const int* p = (const int*)ei + E;
        d0 = p[e0];
        if (e0 + 1 < E) d1 = p[e0 + 1];
    }
    int r0 = atomicAdd(&g_cnt[d0], 1);
    g_rank[e0] = r0;
    if (d1 >= 0) {
        int r1 = atomicAdd(&g_cnt[d1], 1);
        g_rank[e0 + 1] = r1;
    }
}

__global__ void scan1_kernel() {        // per-chunk exclusive scan, 1024 threads
    __shared__ int s[1024];
    int tid = threadIdx.x;
    int i = blockIdx.x * 1024 + tid;
    int v = (i < N_NODES) ? g_cnt[i] : 0;
    s[tid] = v;
    __syncthreads();
    #pragma unroll
    for (int off = 1; off < 1024; off <<= 1) {
        int t = (tid >= off) ? s[tid - off] : 0;
        __syncthreads();
        s[tid] += t;
        __syncthreads();
    }
    g_part[i] = s[tid] - v;             // exclusive
    if (tid == 1023) g_ctot[blockIdx.x] = s[1023];
}

__global__ void scan3_kernel() {        // adds chunk offsets (each block scans totals)
    __shared__ int s[128];
    int tid = threadIdx.x;
    if (tid < 128) {
        int v = (tid < SCAN_CHUNKS) ? g_ctot[tid] : 0;
        s[tid] = v;
    }
    __syncthreads();
    #pragma unroll
    for (int off = 1; off < 128; off <<= 1) {
        int t = (tid < 128 && tid >= off) ? s[tid - off] : 0;
        __syncthreads();
        if (tid < 128) s[tid] += t;
        __syncthreads();
    }
    int coff = (blockIdx.x == 0) ? 0 : s[blockIdx.x - 1];
    int i = blockIdx.x * 1024 + tid;
    if (i < N_NODES) g_rowptr[i] = g_part[i] + coff;
    if (blockIdx.x == 0 && tid == 0) g_rowptr[N_NODES] = s[SCAN_CHUNKS - 1];
}

// fill: pos = rowptr[dst] + rank[e] — no atomics. Also re-zeros g_cnt.
__global__ void fill_kernel(const void* __restrict__ ei, int E) {
    int t = blockIdx.x * blockDim.x + threadIdx.x;
    if (t < N_NODES / 4) ((int4*)g_cnt)[t] = make_int4(0, 0, 0, 0);
    int e0 = t * 2;
    if (e0 >= E) return;
    int is64 = detect_is64((const int*)ei);
    int s0, d0, s1 = -1, d1 = -1;
    if (is64) {
        const long long* p = (const long long*)ei;
        s0 = (int)p[e0]; d0 = (int)p[E + e0];
        if (e0 + 1 < E) { s1 = (int)p[e0 + 1]; d1 = (int)p[E + e0 + 1]; }
    } else {
        const int* p = (const int*)ei;
        s0 = p[e0]; d0 = p[E + e0];
        if (e0 + 1 < E) { s1 = p[e0 + 1]; d1 = p[E + e0 + 1]; }
    }
    int p0 = g_rowptr[d0] + g_rank[e0];
    g_col[p0] = s0;
    if (d1 >= 0) {
        int p1 = g_rowptr[d1] + g_rank[e0 + 1];
        g_col[p1] = s1;
    }
}

// ---------------- pipelined packed-f32x2 dual-output GEMM ----------------
// [tA|uB] = src @ [Wa|Wb], src rows 64 wide, each output OUTT wide.
// LAYER selects device-global src/dst INSIDE device code.
#define FMA2(acc, a2, b2) \
    asm("fma.rn.f32x2 %0, %1, %2, %0;" : "+l"(acc) : "l"(a2), "l"(b2))

template<int OUTT, int LAYER>
__global__ __launch_bounds__(256, 2)
void gemm_dual_kernel(const float* __restrict__ xsrc,
                      const float* __restrict__ Wa,   // [64, OUTT]
                      const float* __restrict__ Wb) { // [64, OUTT]
    constexpr int OUT = 2 * OUTT;          // 128 or 64
    constexpr int TPN = OUT / 16;          // 8 or 4 threads per node
    constexpr int NB  = 8192 / OUT;        // 64 or 128 nodes per block
    constexpr int HALF = NB / 2;
    constexpr int FP  = 33;
    constexpr int NF4 = NB / 32;           // feature float4 per thread (2 or 4)
    constexpr int NW4 = OUT / 32;          // weight float4 per thread (4 or 2)
    constexpr int JQW = OUT / 4;           // float4 per weight row

    const float* src = (LAYER == 1) ? xsrc : g_h;
    float* dstA = (LAYER == 1) ? g_t1 : g_t2;
    float* dstB = (LAYER == 1) ? g_u1 : g_u2;

    __shared__ float sF[NB * FP];
    __shared__ float sW[32 * OUT];

    int tid = threadIdx.x;
    int base = blockIdx.x * NB;
    int ln = tid / TPN;
    int q  = tid % TPN;
    int k4 = tid & 7;

    int r_[NF4], nc_[NF4];
    #pragma unroll
    for (int it = 0; it < NF4; it++) {
        r_[it] = (tid + it * 256) >> 3;
        int n = base + r_[it];
        nc_[it] = (n < N_NODES) ? n : (N_NODES - 1);
    }
    float4 pf[NF4], pw[NW4];

    auto load_chunk = [&](int c) {
        #pragma unroll
        for (int it = 0; it < NF4; it++)
            pf[it] = *(const float4*)(src + (size_t)nc_[it] * 64 + c * 32 + k4 * 4);
        #pragma unroll
        for (int iw = 0; iw < NW4; iw++) {
            int idx = tid + iw * 256;
            int kk = idx / JQW, jq = idx % JQW;
            int k = c * 32 + kk;
            const float* wsrc = (jq < OUTT / 4) ? (Wa + k * OUTT + jq * 4)
                                                : (Wb + k * OUTT + jq * 4 - OUTT);
            pw[iw] = *(const float4*)wsrc;
        }
    };
    auto store_stage = [&]() {
        #pragma unroll
        for (int it = 0; it < NF4; it++) {
            float* d = sF + r_[it] * FP + k4 * 4;
            d[0] = pf[it].x; d[1] = pf[it].y; d[2] = pf[it].z; d[3] = pf[it].w;
        }
        #pragma unroll
        for (int iw = 0; iw < NW4; iw++)
            ((float4*)sW)[tid + iw * 256] = pw[iw];
    };

    load_chunk(0);
    store_stage();
    __syncthreads();

    unsigned long long acc0[8] = {}, acc1[8] = {};
    const float* fp0 = sF + ln * FP;
    const float* fp1 = sF + (ln + HALF) * FP;
    const float* wq  = sW + (q << 2);

    #pragma unroll 1
    for (int c = 0; c < 2; c++) {
        if (c < 1) load_chunk(1);
        #pragma unroll 8
        for (int kk = 0; kk < 32; kk++) {
            float f0 = fp0[kk], f1 = fp1[kk];
            unsigned long long f0d, f1d;
            asm("mov.b64 %0, {%1,%1};" : "=l"(f0d) : "f"(f0));
            asm("mov.b64 %0, {%1,%1};" : "=l"(f1d) : "f"(f1));
            const float* wr = wq + kk * OUT;
            #pragma unroll
            for (int j8 = 0; j8 < 4; j8++) {
                ulonglong2 w = *(const ulonglong2*)(wr + j8 * TPN * 4);
                FMA2(acc0[j8 * 2],     f0d, w.x);
                FMA2(acc0[j8 * 2 + 1], f0d, w.y);
                FMA2(acc1[j8 * 2],     f1d, w.x);
                FMA2(acc1[j8 * 2 + 1], f1d, w.y);
            }
        }
        __syncthreads();
        if (c < 1) { store_stage(); __syncthreads(); }
    }

    int n0 = base + ln, n1 = base + ln + HALF;
    #pragma unroll
    for (int j8 = 0; j8 < 4; j8++) {
        int jb = j8 * TPN * 4 + (q << 2);
        float* dst = (j8 < 2) ? dstA : dstB;
        int joff = (j8 < 2) ? jb : jb - OUTT;
        if (n0 < N_NODES) {
            float o[4];
            asm("mov.b64 {%0,%1}, %2;" : "=f"(o[0]), "=f"(o[1]) : "l"(acc0[j8 * 2]));
            asm("mov.b64 {%0,%1}, %2;" : "=f"(o[2]), "=f"(o[3]) : "l"(acc0[j8 * 2 + 1]));
            *(float4*)(dst + (size_t)n0 * OUTT + joff) = *(float4*)o;
        }
        if (n1 < N_NODES) {
            float o[4];
            asm("mov.b64 {%0,%1}, %2;" : "=f"(o[0]), "=f"(o[1]) : "l"(acc1[j8 * 2]));
            asm("mov.b64 {%0,%1}, %2;" : "=f"(o[2]), "=f"(o[3]) : "l"(acc1[j8 * 2 + 1]));
            *(float4*)(dst + (size_t)n1 * OUTT + joff) = *(float4*)o;
        }
    }
}

// ---------------- gather-mean + epilogue kernels ----------------
// layer 1: h = relu(mean_gather(t1) + u1 + b1); rows 64 wide; 16 lanes/node.
__global__ __launch_bounds__(256)
void aggH_kernel(const float* __restrict__ b1) {
    int tid = threadIdx.x;
    int g = tid >> 4;
    int c = tid & 15;
    int n = blockIdx.x * 16 + g;
    if (n >= N_NODES) return;
    int start = g_rowptr[n], end = g_rowptr[n + 1];
    float4 acc = make_float4(0.f, 0.f, 0.f, 0.f);
    int i = start;
    for (; i + 3 < end; i += 4) {
        int s0 = g_col[i], s1 = g_col[i + 1], s2 = g_col[i + 2], s3 = g_col[i + 3];
        float4 v0 = *(const float4*)(g_t1 + (size_t)s0 * 64 + c * 4);
        float4 v1 = *(const float4*)(g_t1 + (size_t)s1 * 64 + c * 4);
        float4 v2 = *(const float4*)(g_t1 + (size_t)s2 * 64 + c * 4);
        float4 v3 = *(const float4*)(g_t1 + (size_t)s3 * 64 + c * 4);
        acc.x += (v0.x + v1.x) + (v2.x + v3.x);
        acc.y += (v0.y + v1.y) + (v2.y + v3.y);
        acc.z += (v0.z + v1.z) + (v2.z + v3.z);
        acc.w += (v0.w + v1.w) + (v2.w + v3.w);
    }
    for (; i < end; i++) {
        int s0 = g_col[i];
        float4 v0 = *(const float4*)(g_t1 + (size_t)s0 * 64 + c * 4);
        acc.x += v0.x; acc.y += v0.y; acc.z += v0.z; acc.w += v0.w;
    }
    float inv = 1.0f / fmaxf((float)(end - start), 1.0f);
    float4 u = *(const float4*)(g_u1 + (size_t)n * 64 + c * 4);
    float4 bb = *(const float4*)(b1 + c * 4);
    float4 o;
    o.x = fmaxf(fmaf(acc.x, inv, u.x + bb.x), 0.0f);
    o.y = fmaxf(fmaf(acc.y, inv, u.y + bb.y), 0.0f);
    o.z = fmaxf(fmaf(acc.z, inv, u.z + bb.z), 0.0f);
    o.w = fmaxf(fmaf(acc.w, inv, u.w + bb.w), 0.0f);
    *(float4*)(g_h + (size_t)n * 64 + c * 4) = o;
}

// layer 2: out = mean_gather(t2) + u2 + b2; rows 32 wide; 8 lanes/node.
__global__ __launch_bounds__(256)
void agg_final_kernel(const float* __restrict__ b2, float* __restrict__ out) {
    int tid = threadIdx.x;
    int g = tid >> 3;
    int c = tid & 7;
    int n = blockIdx.x * 32 + g;
    if (n >= N_NODES) return;
    int start = g_rowptr[n], end = g_rowptr[n + 1];
    float4 acc = make_float4(0.f, 0.f, 0.f, 0.f);
    int i = start;
    for (; i + 3 < end; i += 4) {
        int s0 = g_col[i], s1 = g_col[i + 1], s2 = g_col[i + 2], s3 = g_col[i + 3];
        float4 v0 = *(const float4*)(g_t2 + (size_t)s0 * 32 + c * 4);
        float4 v1 = *(const float4*)(g_t2 + (size_t)s1 * 32 + c * 4);
        float4 v2 = *(const float4*)(g_t2 + (size_t)s2 * 32 + c * 4);
        float4 v3 = *(const float4*)(g_t2 + (size_t)s3 * 32 + c * 4);
        acc.x += (v0.x + v1.x) + (v2.x + v3.x);
        acc.y += (v0.y + v1.y) + (v2.y + v3.y);
        acc.z += (v0.z + v1.z) + (v2.z + v3.z);
        acc.w += (v0.w + v1.w) + (v2.w + v3.w);
    }
    for (; i < end; i++) {
        int s0 = g_col[i];
        float4 v0 = *(const float4*)(g_t2 + (size_t)s0 * 32 + c * 4);
        acc.x += v0.x; acc.y += v0.y; acc.z += v0.z; acc.w += v0.w;
    }
    float inv = 1.0f / fmaxf((float)(end - start), 1.0f);
    float4 u = *(const float4*)(g_u2 + (size_t)n * 32 + c * 4);
    float4 bb = *(const float4*)(b2 + c * 4);
    float4 o;
    o.x = fmaf(acc.x, inv, u.x + bb.x);
    o.y = fmaf(acc.y, inv, u.y + bb.y);
    o.z = fmaf(acc.z, inv, u.z + bb.z);
    o.w = fmaf(acc.w, inv, u.w + bb.w);
    *(float4*)(out + (size_t)n * 32 + c * 4) = o;
}

// ---------------- launch ----------------
extern "C" void kernel_launch(void* const* d_in, const int* in_sizes, int n_in,
                              void* d_out, int out_size) {
    const float* x   = (const float*)d_in[0];
    const void*  ei  = d_in[1];
    const float* W1n = (const float*)d_in[2];
    const float* W1s = (const float*)d_in[3];
    const float* b1  = (const float*)d_in[4];
    const float* W2n = (const float*)d_in[5];
    const float* W2s = (const float*)d_in[6];
    const float* b2  = (const float*)d_in[7];
    float* out = (float*)d_out;
    int E = in_sizes[1] / 2;

    // Fork a side stream inside capture: CSR build runs concurrently with
    // the layer-1 GEMM (they are independent).
    cudaStream_t s2;
    cudaStreamCreate(&s2);
    cudaEvent_t evFork, evJoin;
    cudaEventCreateWithFlags(&evFork, cudaEventDisableTiming);
    cudaEventCreateWithFlags(&evJoin, cudaEventDisableTiming);

    cudaEventRecord(evFork, 0);          // null (capture) stream
    cudaStreamWaitEvent(s2, evFork, 0);

    // CSR build on side stream
    count_kernel<<<(E / 2 + 256) / 256, 256, 0, s2>>>(ei, E);
    scan1_kernel<<<SCAN_CHUNKS, 1024, 0, s2>>>();
    scan3_kernel<<<SCAN_CHUNKS, 1024, 0, s2>>>();
    fill_kernel<<<(E / 2 + 256) / 256, 256, 0, s2>>>(ei, E);
    cudaEventRecord(evJoin, s2);

    // layer-1 GEMM on main stream, concurrent with CSR build
    gemm_dual_kernel<64, 1><<<(N_NODES + 63) / 64, 256>>>(x, W1n, W1s);

    // join: aggregation needs both CSR and t1/u1
    cudaStreamWaitEvent(0, evJoin, 0);

    aggH_kernel<<<(N_NODES + 15) / 16, 256>>>(b1);
    gemm_dual_kernel<32, 2><<<(N_NODES + 127) / 128, 256>>>(nullptr, W2n, W2s);
    agg_final_kernel<<<(N_NODES + 31) / 32, 256>>>(b2, out);

    cudaEventDestroy(evFork);
    cudaEventDestroy(evJoin);
    cudaStreamDestroy(s2);
}